// round 1
// baseline (speedup 1.0000x reference)
#include <cuda_runtime.h>
#include <math_constants.h>

#define Hdim 768
#define NTH 256
#define SPLITS 32
#define WIN 15
#define WLEN 31
#define MAXB 16

// ---------------- scratch (no allocation allowed) ----------------
__device__ int   g_is64;
__device__ float g_pmax[MAXB * Hdim * SPLITS];
__device__ float g_psum[MAXB * Hdim * SPLITS];
__device__ float g_pcnt[MAXB * SPLITS];
__device__ float g_tmax[MAXB * Hdim];
__device__ float g_tavg[MAXB * Hdim];

// flag-dispatched integer load (int64 vs int32 storage)
__device__ __forceinline__ long long ld_int(const void* p, long long i, int is64) {
    return is64 ? ((const long long*)p)[i] : (long long)((const int*)p)[i];
}

// ---------------- dtype detection ----------------
// word_mask values are 0/1. If storage is int32, an int64 view over pairs
// produces values outside {0,1} with overwhelming probability.
__global__ void detect_kernel(const void* wm, int nscan64) {
    __shared__ int bad;
    if (threadIdx.x == 0) bad = 0;
    __syncthreads();
    const long long* p = (const long long*)wm;
    int mybad = 0;
    for (int i = threadIdx.x; i < nscan64; i += blockDim.x) {
        long long v = p[i];
        if (v < 0 || v > 1) mybad = 1;
    }
    if (mybad) atomicOr(&bad, 1);
    __syncthreads();
    if (threadIdx.x == 0) g_is64 = bad ? 0 : 1;
}

// ---------------- stage 1: streaming masked max/sum over S ----------------
// grid: (H/256, SPLITS, B), block: 256. Thread = one h column; loop over S chunk.
__global__ void __launch_bounds__(NTH) text_reduce_kernel(
    const float* __restrict__ seq, const void* __restrict__ tt,
    const void* __restrict__ wm, int S)
{
    const int hc    = blockIdx.x;
    const int split = blockIdx.y;
    const int b     = blockIdx.z;
    const int tid   = threadIdx.x;
    const int is64  = g_is64;
    const int SC    = S / SPLITS;        // 128
    const int s0    = split * SC;

    __shared__ float smask[128];
    for (int i = tid; i < SC; i += NTH) {
        long long s = s0 + i;
        long long t = ld_int(tt, (long long)b * S + s, is64);
        long long w = ld_int(wm, (long long)b * S + s, is64);
        smask[i] = (t == 0 && w != 0) ? 1.0f : 0.0f;
    }
    __syncthreads();

    const int h = hc * NTH + tid;
    const float* base = seq + ((long long)b * S + s0) * Hdim + h;

    float mx = -CUDART_INF_F;
    float sm = 0.0f;
#pragma unroll 8
    for (int i = 0; i < SC; i++) {
        float v = base[(long long)i * Hdim];
        float m = smask[i];
        sm += m * v;
        mx = fmaxf(mx, m > 0.0f ? v : -CUDART_INF_F);
    }

    const int o = (b * Hdim + h) * SPLITS + split;
    g_pmax[o] = mx;
    g_psum[o] = sm;
    if (hc == 0 && tid == 0) {
        float c = 0.0f;
        for (int i = 0; i < SC; i++) c += smask[i];
        g_pcnt[b * SPLITS + split] = c;
    }
}

// ---------------- stage 2: fold split partials ----------------
__global__ void text_finalize_kernel(int B) {
    int idx = blockIdx.x * blockDim.x + threadIdx.x;
    if (idx >= B * Hdim) return;
    int b = idx / Hdim;
    float mx = -CUDART_INF_F, sm = 0.0f, c = 0.0f;
#pragma unroll
    for (int j = 0; j < SPLITS; j++) {
        mx = fmaxf(mx, g_pmax[idx * SPLITS + j]);
        sm += g_psum[idx * SPLITS + j];
        c  += g_pcnt[b * SPLITS + j];
    }
    g_tmax[idx] = fmaxf(mx, 0.0f);
    g_tavg[idx] = sm / c;
}

// ---------------- cls score: dot([pooled, tmax, tavg], cls_W) + b ----------------
__global__ void __launch_bounds__(NTH) cls_kernel(
    const float* __restrict__ pooled, const float* __restrict__ cW,
    const float* __restrict__ cb, float* __restrict__ out, int G)
{
    const int b = blockIdx.x;
    const int tid = threadIdx.x;
    float acc = 0.0f;
    for (int h = tid; h < Hdim; h += NTH) {
        acc += pooled[b * Hdim + h] * cW[h]
             + g_tmax[b * Hdim + h] * cW[Hdim + h]
             + g_tavg[b * Hdim + h] * cW[2 * Hdim + h];
    }
    __shared__ float red[NTH];
    red[tid] = acc;
    __syncthreads();
    for (int s = NTH / 2; s > 0; s >>= 1) {
        if (tid < s) red[tid] += red[tid + s];
        __syncthreads();
    }
    if (tid == 0) out[b * (G + 1)] = red[0] + cb[0];
}

// ---------------- gap scores: window pooling + dot, one block per (b,g) --------
__global__ void __launch_bounds__(NTH) gap_kernel(
    const float* __restrict__ seq, const void* __restrict__ tt,
    const void* __restrict__ wm, const void* __restrict__ gids,
    const float* __restrict__ gW, const float* __restrict__ gb,
    float* __restrict__ out, int S, int G)
{
    const int g = blockIdx.x;
    const int b = blockIdx.y;
    const int tid = threadIdx.x;
    const int is64 = g_is64;

    __shared__ int   sgidx;
    __shared__ float smask[WLEN];
    __shared__ float scnt;

    if (tid == 0) sgidx = (int)ld_int(gids, (long long)b * G + g, is64);
    __syncthreads();
    const int gidx = sgidx;

    if (tid < WLEN) {
        int s = gidx - WIN + tid;
        float m = 0.0f;
        if (s >= 0 && s < S) {
            long long t = ld_int(tt, (long long)b * S + s, is64);
            long long w = ld_int(wm, (long long)b * S + s, is64);
            m = (t == 0 && w != 0) ? 1.0f : 0.0f;
        }
        smask[tid] = m;
    }
    __syncthreads();
    if (tid == 0) {
        float c = 0.0f;
        for (int i = 0; i < WLEN; i++) c += smask[i];
        scnt = c;
    }
    __syncthreads();
    const float cnt = scnt;

    float acc = 0.0f;
    const float* rowb = seq + (long long)b * S * Hdim;
    for (int h = tid; h < Hdim; h += NTH) {
        float gv = rowb[(long long)gidx * Hdim + h];
        float mx = -CUDART_INF_F, sm = 0.0f;
#pragma unroll
        for (int w2 = 0; w2 < WLEN; w2++) {
            int s = gidx - WIN + w2;
            int sc = s < 0 ? 0 : (s >= S ? S - 1 : s);
            float v = rowb[(long long)sc * Hdim + h];
            float m = smask[w2];
            sm += m * v;
            mx = fmaxf(mx, m > 0.0f ? v : -CUDART_INF_F);
        }
        acc += gv * gW[h]
             + fmaxf(mx, 0.0f) * gW[Hdim + h]
             + (sm / cnt) * gW[2 * Hdim + h];
    }

    __shared__ float red[NTH];
    red[tid] = acc;
    __syncthreads();
    for (int s = NTH / 2; s > 0; s >>= 1) {
        if (tid < s) red[tid] += red[tid + s];
        __syncthreads();
    }
    if (tid == 0) out[b * (G + 1) + 1 + g] = red[0] + gb[0];
}

// ---------------- launch ----------------
extern "C" void kernel_launch(void* const* d_in, const int* in_sizes, int n_in,
                              void* d_out, int out_size)
{
    const float* seq    = (const float*)d_in[0];
    const float* pooled = (const float*)d_in[1];
    const void*  tt     = d_in[2];
    const void*  wm     = d_in[3];
    const void*  gids   = d_in[4];
    const float* gW     = (const float*)d_in[5];
    const float* gb     = (const float*)d_in[6];
    const float* cW     = (const float*)d_in[7];
    const float* cb     = (const float*)d_in[8];
    float* out = (float*)d_out;

    const int B = in_sizes[1] / Hdim;   // 16
    const int S = in_sizes[2] / B;      // 4096
    const int G = in_sizes[4] / B;      // 16

    detect_kernel<<<1, 256>>>(wm, in_sizes[3] / 2);

    dim3 grid1(Hdim / NTH, SPLITS, B);
    text_reduce_kernel<<<grid1, NTH>>>(seq, tt, wm, S);

    text_finalize_kernel<<<(B * Hdim + NTH - 1) / NTH, NTH>>>(B);

    cls_kernel<<<B, NTH>>>(pooled, cW, cb, out, G);

    gap_kernel<<<dim3(G, B), NTH>>>(seq, tt, wm, gids, gW, gb, out, S, G);
}

// round 2
// speedup vs baseline: 2.0203x; 2.0203x over previous
#include <cuda_runtime.h>
#include <math_constants.h>

#define Hdim 768
#define H4   192            // Hdim/4
#define SPL  64             // S splits for stage-1
#define WIN  15
#define WLEN 31
#define MAXB 16

// ---------------- scratch (no allocation allowed) ----------------
__device__ int   g_is64;
__device__ float g_pmax[MAXB * SPL * Hdim];   // [b][split][h]
__device__ float g_psum[MAXB * SPL * Hdim];
__device__ float g_pcnt[MAXB * SPL];

// flag-dispatched integer load (int64 vs int32 storage)
__device__ __forceinline__ long long ld_int(const void* p, long long i, int is64) {
    return is64 ? ((const long long*)p)[i] : (long long)((const int*)p)[i];
}

// ---------------- dtype detection (cheap) ----------------
// word_mask values are 0/1. If storage were int32, an int64 view of a pair
// (a,b) = a + (b<<32) exceeds 1 whenever b==1; scanning 512 random pairs
// misses with probability 2^-512.
__global__ void detect_kernel(const long long* __restrict__ wm, int npairs) {
    __shared__ int sb;
    if (threadIdx.x == 0) sb = 0;
    __syncthreads();
    int bad = 0;
    for (int i = threadIdx.x; i < npairs; i += blockDim.x) {
        long long v = wm[i];
        if (v < 0 || v > 1) bad = 1;
    }
    if (bad) atomicOr(&sb, 1);
    __syncthreads();
    if (threadIdx.x == 0) g_is64 = sb ? 0 : 1;
}

// ---------------- stage 1: streaming masked max/sum over S ----------------
// grid (SPL, B), block 192. Thread = one float4 column of H; loop over S chunk.
__global__ void __launch_bounds__(H4) text_reduce_kernel(
    const float4* __restrict__ seqv, const void* __restrict__ tt,
    const void* __restrict__ wm, int S)
{
    const int split = blockIdx.x;
    const int b     = blockIdx.y;
    const int tid   = threadIdx.x;
    const int is64  = g_is64;
    const int SC    = S / SPL;              // 64
    const int s0    = split * SC;

    __shared__ float smask[64];
    if (tid < SC) {
        long long s = (long long)b * S + s0 + tid;
        long long t = ld_int(tt, s, is64);
        long long w = ld_int(wm, s, is64);
        smask[tid] = (t == 0 && w != 0) ? 1.0f : 0.0f;
    }
    __syncthreads();

    const float4* base = seqv + (long long)(b * S + s0) * H4 + tid;

    float4 mx = make_float4(0.f, 0.f, 0.f, 0.f);
    float4 sm = make_float4(0.f, 0.f, 0.f, 0.f);
#pragma unroll 8
    for (int i = 0; i < SC; i++) {
        float4 v = base[(long long)i * H4];
        float  m = smask[i];
        float ax = m * v.x, ay = m * v.y, az = m * v.z, aw = m * v.w;
        sm.x += ax; sm.y += ay; sm.z += az; sm.w += aw;
        mx.x = fmaxf(mx.x, ax); mx.y = fmaxf(mx.y, ay);
        mx.z = fmaxf(mx.z, az); mx.w = fmaxf(mx.w, aw);
    }

    const int o = (b * SPL + split) * H4 + tid;     // float4 index
    ((float4*)g_pmax)[o] = mx;
    ((float4*)g_psum)[o] = sm;
    if (tid == 0) {
        float c = 0.0f;
        for (int i = 0; i < SC; i++) c += smask[i];
        g_pcnt[b * SPL + split] = c;
    }
}

// ---------------- tail: finalize + cls (block x==0), gap (x-1) ------------
__global__ void __launch_bounds__(256) tail_kernel(
    const float* __restrict__ seq, const float* __restrict__ pooled,
    const void* __restrict__ tt,  const void* __restrict__ wm,
    const void* __restrict__ gids,
    const float* __restrict__ gW, const float* __restrict__ gb,
    const float* __restrict__ cW, const float* __restrict__ cb,
    float* __restrict__ out, int S, int G)
{
    const int b   = blockIdx.y;
    const int tid = threadIdx.x;
    __shared__ float red[256];

    if (blockIdx.x == 0) {
        // ---- cls score ----
        __shared__ float scnt;
        if (tid < 32) {
            float c = 0.0f;
            for (int j = tid; j < SPL; j += 32) c += g_pcnt[b * SPL + j];
#pragma unroll
            for (int o = 16; o; o >>= 1) c += __shfl_xor_sync(0xffffffffu, c, o);
            if (tid == 0) scnt = c;
        }
        __syncthreads();
        const float inv = 1.0f / scnt;

        float acc = 0.0f;
#pragma unroll
        for (int h = tid; h < Hdim; h += 256) {
            float mx = 0.0f, sm = 0.0f;
#pragma unroll 8
            for (int j = 0; j < SPL; j++) {
                mx = fmaxf(mx, g_pmax[(b * SPL + j) * Hdim + h]);
                sm += g_psum[(b * SPL + j) * Hdim + h];
            }
            acc += pooled[b * Hdim + h] * cW[h]
                 + mx * cW[Hdim + h]
                 + sm * inv * cW[2 * Hdim + h];
        }
        red[tid] = acc;
        __syncthreads();
        for (int s = 128; s > 0; s >>= 1) {
            if (tid < s) red[tid] += red[tid + s];
            __syncthreads();
        }
        if (tid == 0) out[b * (G + 1)] = red[0] + cb[0];
    } else {
        // ---- gap score ----
        const int g    = blockIdx.x - 1;
        const int is64 = g_is64;
        __shared__ int   sgidx;
        __shared__ float smk[WLEN];
        __shared__ float scnt2;

        if (tid == 0) sgidx = (int)ld_int(gids, (long long)b * G + g, is64);
        __syncthreads();
        const int gidx = sgidx;

        if (tid < WLEN) {
            int s = gidx - WIN + tid;
            float m = 0.0f;
            if (s >= 0 && s < S) {
                long long t = ld_int(tt, (long long)b * S + s, is64);
                long long w = ld_int(wm, (long long)b * S + s, is64);
                m = (t == 0 && w != 0) ? 1.0f : 0.0f;
            }
            smk[tid] = m;
        }
        __syncthreads();
        if (tid == 0) {
            float c = 0.0f;
            for (int i = 0; i < WLEN; i++) c += smk[i];
            scnt2 = c;
        }
        __syncthreads();

        float acc = 0.0f;
        if (tid < H4) {
            const float4* rowb = (const float4*)seq + (long long)b * S * H4;
            float4 gv = rowb[(long long)gidx * H4 + tid];
            float4 mx = make_float4(0.f, 0.f, 0.f, 0.f);
            float4 sm = make_float4(0.f, 0.f, 0.f, 0.f);
#pragma unroll
            for (int w2 = 0; w2 < WLEN; w2++) {
                int s  = gidx - WIN + w2;
                int sc = s < 0 ? 0 : (s >= S ? S - 1 : s);
                float4 v = rowb[(long long)sc * H4 + tid];
                float  m = smk[w2];
                float ax = m * v.x, ay = m * v.y, az = m * v.z, aw = m * v.w;
                sm.x += ax; sm.y += ay; sm.z += az; sm.w += aw;
                mx.x = fmaxf(mx.x, ax); mx.y = fmaxf(mx.y, ay);
                mx.z = fmaxf(mx.z, az); mx.w = fmaxf(mx.w, aw);
            }
            const float invc = 1.0f / scnt2;
            const int h = 4 * tid;
            acc = gv.x * gW[h]     + gv.y * gW[h + 1]
                + gv.z * gW[h + 2] + gv.w * gW[h + 3]
                + mx.x * gW[Hdim + h]     + mx.y * gW[Hdim + h + 1]
                + mx.z * gW[Hdim + h + 2] + mx.w * gW[Hdim + h + 3]
                + sm.x * invc * gW[2 * Hdim + h]     + sm.y * invc * gW[2 * Hdim + h + 1]
                + sm.z * invc * gW[2 * Hdim + h + 2] + sm.w * invc * gW[2 * Hdim + h + 3];
        }
        red[tid] = acc;
        __syncthreads();
        for (int s = 128; s > 0; s >>= 1) {
            if (tid < s) red[tid] += red[tid + s];
            __syncthreads();
        }
        if (tid == 0) out[b * (G + 1) + 1 + g] = red[0] + gb[0];
    }
}

// ---------------- launch ----------------
extern "C" void kernel_launch(void* const* d_in, const int* in_sizes, int n_in,
                              void* d_out, int out_size)
{
    const float* seq    = (const float*)d_in[0];
    const float* pooled = (const float*)d_in[1];
    const void*  tt     = d_in[2];
    const void*  wm     = d_in[3];
    const void*  gids   = d_in[4];
    const float* gW     = (const float*)d_in[5];
    const float* gb     = (const float*)d_in[6];
    const float* cW     = (const float*)d_in[7];
    const float* cb     = (const float*)d_in[8];
    float* out = (float*)d_out;

    const int B = in_sizes[1] / Hdim;   // 16
    const int S = in_sizes[2] / B;      // 4096
    const int G = in_sizes[4] / B;      // 16

    int npairs = in_sizes[3] / 2;
    if (npairs > 512) npairs = 512;
    detect_kernel<<<1, 256>>>((const long long*)wm, npairs);

    text_reduce_kernel<<<dim3(SPL, B), H4>>>((const float4*)seq, tt, wm, S);

    tail_kernel<<<dim3(G + 1, B), 256>>>(seq, pooled, tt, wm, gids,
                                         gW, gb, cW, cb, out, S, G);
}

// round 4
// speedup vs baseline: 3.2215x; 1.5945x over previous
#include <cuda_runtime.h>
#include <math_constants.h>

#define Hdim 768
#define H4   192            // Hdim/4
#define SPL  64             // S splits for stage-1
#define WIN  15
#define WLEN 31
#define MAXB 16

// ---------------- scratch (no allocation allowed) ----------------
__device__ int   g_is64;
__device__ float g_pmax[MAXB * SPL * Hdim];   // [b][split][h]
__device__ float g_psum[MAXB * SPL * Hdim];
__device__ float g_pcnt[MAXB * SPL];

// flag-dispatched integer load (int64 vs int32 storage)
__device__ __forceinline__ long long ld_int(const void* p, long long i, int is64) {
    return is64 ? ((const long long*)p)[i] : (long long)((const int*)p)[i];
}

// Per-warp dtype detection: scan a fixed 256-pair region of word_mask viewed
// as int64. If storage were int32, pair = lo + (hi<<32) with hi in {0,1}
// random -> value > 1 unless all 256 his are 0 (P = 2^-256). Region is the
// same for every block -> L2-resident, deterministic.
__device__ __forceinline__ int warp_detect_is64(const void* wm, int lane) {
    const long long* p = (const long long*)wm;
    int bad = 0;
#pragma unroll
    for (int i = 0; i < 8; i++) {
        long long v = p[lane + 32 * i];
        if (v < 0 || v > 1) bad = 1;
    }
    unsigned bm = __ballot_sync(0xffffffffu, bad);
    return bm ? 0 : 1;
}

// ---------------- stage 1: compacted streaming max/sum over S -------------
// grid (SPL, B), block 192 (= H4). Thread = one float4 column of H.
// Only rows with base_mask=1 are loaded (saves ~50% of HBM traffic).
__global__ void __launch_bounds__(H4) text_reduce_kernel(
    const float4* __restrict__ seqv, const void* __restrict__ tt,
    const void* __restrict__ wm, int S)
{
    const int split = blockIdx.x;
    const int b     = blockIdx.y;
    const int tid   = threadIdx.x;
    const int SC    = S / SPL;              // 64
    const int s0    = split * SC;

    __shared__ int s_is64;
    __shared__ int slist[64];
    __shared__ int s_cnt;

    if (tid < 32) {
        // detect dtype
        int is64 = warp_detect_is64(wm, tid);
        if (tid == 0) { s_is64 = is64; g_is64 = is64; }
        // build compacted row list (deterministic ascending order)
        int base = 0;
        for (int j = 0; j < SC; j += 32) {
            int row = j + tid;
            long long s = (long long)b * S + s0 + row;
            long long t = ld_int(tt, s, is64);
            long long w = ld_int(wm, s, is64);
            int m = (t == 0 && w != 0);
            unsigned bal = __ballot_sync(0xffffffffu, m);
            if (m) slist[base + __popc(bal & ((1u << tid) - 1u))] = row;
            base += __popc(bal);
        }
        if (tid == 0) s_cnt = base;
    }
    __syncthreads();

    const int cnt = s_cnt;
    const float4* base4 = seqv + (long long)(b * S + s0) * H4 + tid;

    float4 mx = make_float4(0.f, 0.f, 0.f, 0.f);
    float4 sm = make_float4(0.f, 0.f, 0.f, 0.f);
#pragma unroll 4
    for (int i = 0; i < cnt; i++) {
        float4 v = base4[(long long)slist[i] * H4];
        sm.x += v.x; sm.y += v.y; sm.z += v.z; sm.w += v.w;
        mx.x = fmaxf(mx.x, v.x); mx.y = fmaxf(mx.y, v.y);
        mx.z = fmaxf(mx.z, v.z); mx.w = fmaxf(mx.w, v.w);
    }

    const int o = (b * SPL + split) * H4 + tid;     // float4 index
    ((float4*)g_pmax)[o] = mx;
    ((float4*)g_psum)[o] = sm;
    if (tid == 0) g_pcnt[b * SPL + split] = (float)cnt;
}

// ---------------- tail: finalize+cls (block x==0), gap (x-1) ---------------
__global__ void __launch_bounds__(256) tail_kernel(
    const float4* __restrict__ seqv, const float* __restrict__ pooled,
    const void* __restrict__ tt,  const void* __restrict__ wm,
    const void* __restrict__ gids,
    const float* __restrict__ gW, const float* __restrict__ gb,
    const float* __restrict__ cW, const float* __restrict__ cb,
    float* __restrict__ out, int S, int G)
{
    const int b   = blockIdx.y;
    const int tid = threadIdx.x;
    __shared__ float red[256];

    if (blockIdx.x == 0) {
        // ---- cls score ----
        __shared__ float scnt;
        if (tid < 32) {
            float c = 0.0f;
            for (int j = tid; j < SPL; j += 32) c += g_pcnt[b * SPL + j];
#pragma unroll
            for (int o = 16; o; o >>= 1) c += __shfl_xor_sync(0xffffffffu, c, o);
            if (tid == 0) scnt = c;
        }
        __syncthreads();
        const float inv = 1.0f / scnt;

        float acc = 0.0f;
        if (tid < H4) {
            const float4* pmax4 = (const float4*)g_pmax;
            const float4* psum4 = (const float4*)g_psum;
            float4 mx = make_float4(0.f, 0.f, 0.f, 0.f);
            float4 sm = make_float4(0.f, 0.f, 0.f, 0.f);
#pragma unroll 8
            for (int j = 0; j < SPL; j++) {
                float4 a = pmax4[(b * SPL + j) * H4 + tid];
                float4 s = psum4[(b * SPL + j) * H4 + tid];
                mx.x = fmaxf(mx.x, a.x); mx.y = fmaxf(mx.y, a.y);
                mx.z = fmaxf(mx.z, a.z); mx.w = fmaxf(mx.w, a.w);
                sm.x += s.x; sm.y += s.y; sm.z += s.z; sm.w += s.w;
            }
            const int h = 4 * tid;
            acc = pooled[b * Hdim + h]     * cW[h]
                + pooled[b * Hdim + h + 1] * cW[h + 1]
                + pooled[b * Hdim + h + 2] * cW[h + 2]
                + pooled[b * Hdim + h + 3] * cW[h + 3]
                + mx.x * cW[Hdim + h]     + mx.y * cW[Hdim + h + 1]
                + mx.z * cW[Hdim + h + 2] + mx.w * cW[Hdim + h + 3]
                + sm.x * inv * cW[2 * Hdim + h]     + sm.y * inv * cW[2 * Hdim + h + 1]
                + sm.z * inv * cW[2 * Hdim + h + 2] + sm.w * inv * cW[2 * Hdim + h + 3];
        }
        red[tid] = acc;
        __syncthreads();
        for (int s = 128; s > 0; s >>= 1) {
            if (tid < s) red[tid] += red[tid + s];
            __syncthreads();
        }
        if (tid == 0) out[b * (G + 1)] = red[0] + cb[0];
    } else {
        // ---- gap score ----
        const int g    = blockIdx.x - 1;
        const int is64 = g_is64;
        __shared__ int   sgidx;
        __shared__ int   slist[WLEN];
        __shared__ int   s_cnt;

        if (tid == 0) sgidx = (int)ld_int(gids, (long long)b * G + g, is64);
        __syncthreads();
        const int gidx = sgidx;

        if (tid < 32) {
            int s = gidx - WIN + tid;
            int m = 0;
            if (tid < WLEN && s >= 0 && s < S) {
                long long t = ld_int(tt, (long long)b * S + s, is64);
                long long w = ld_int(wm, (long long)b * S + s, is64);
                m = (t == 0 && w != 0);
            }
            unsigned bal = __ballot_sync(0xffffffffu, m);
            if (m) slist[__popc(bal & ((1u << tid) - 1u))] = s;
            if (tid == 0) s_cnt = __popc(bal);
        }
        __syncthreads();
        const int   cnt  = s_cnt;
        const float invc = 1.0f / (float)cnt;

        float acc = 0.0f;
        if (tid < H4) {
            const float4* rowb = seqv + (long long)b * S * H4 + tid;
            float4 gv = rowb[(long long)gidx * H4];
            float4 mx = make_float4(0.f, 0.f, 0.f, 0.f);
            float4 sm = make_float4(0.f, 0.f, 0.f, 0.f);
#pragma unroll 4
            for (int i = 0; i < cnt; i++) {
                float4 v = rowb[(long long)slist[i] * H4];
                sm.x += v.x; sm.y += v.y; sm.z += v.z; sm.w += v.w;
                mx.x = fmaxf(mx.x, v.x); mx.y = fmaxf(mx.y, v.y);
                mx.z = fmaxf(mx.z, v.z); mx.w = fmaxf(mx.w, v.w);
            }
            const int h = 4 * tid;
            acc = gv.x * gW[h]     + gv.y * gW[h + 1]
                + gv.z * gW[h + 2] + gv.w * gW[h + 3]
                + mx.x * gW[Hdim + h]     + mx.y * gW[Hdim + h + 1]
                + mx.z * gW[Hdim + h + 2] + mx.w * gW[Hdim + h + 3]
                + sm.x * invc * gW[2 * Hdim + h]     + sm.y * invc * gW[2 * Hdim + h + 1]
                + sm.z * invc * gW[2 * Hdim + h + 2] + sm.w * invc * gW[2 * Hdim + h + 3];
        }
        red[tid] = acc;
        __syncthreads();
        for (int s = 128; s > 0; s >>= 1) {
            if (tid < s) red[tid] += red[tid + s];
            __syncthreads();
        }
        if (tid == 0) out[b * (G + 1) + 1 + g] = red[0] + gb[0];
    }
}

// ---------------- launch ----------------
extern "C" void kernel_launch(void* const* d_in, const int* in_sizes, int n_in,
                              void* d_out, int out_size)
{
    const float* seq    = (const float*)d_in[0];
    const float* pooled = (const float*)d_in[1];
    const void*  tt     = d_in[2];
    const void*  wm     = d_in[3];
    const void*  gids   = d_in[4];
    const float* gW     = (const float*)d_in[5];
    const float* gb     = (const float*)d_in[6];
    const float* cW     = (const float*)d_in[7];
    const float* cb     = (const float*)d_in[8];
    float* out = (float*)d_out;

    const int B = in_sizes[1] / Hdim;   // 16
    const int S = in_sizes[2] / B;      // 4096
    const int G = in_sizes[4] / B;      // 16

    text_reduce_kernel<<<dim3(SPL, B), H4>>>((const float4*)seq, tt, wm, S);

    tail_kernel<<<dim3(G + 1, B), 256>>>((const float4*)seq, pooled, tt, wm,
                                         gids, gW, gb, cW, cb, out, S, G);
}